// round 9
// baseline (speedup 1.0000x reference)
#include <cuda_runtime.h>
#include <cuda_fp16.h>
#include <cuda_bf16.h>
#include <math.h>

#define NSEG 17          // labels 0..16 (bin 0 = background, excluded from loss)
#define NBIN 16          // bins 1..16
#define NB   16          // batch
#define TPB  256
#define GX   37          // blocks per batch image
#define NBLK (GX * NB)   // 592 blocks = 148 SMs * 4
#define SIGMA_DIS 3.0f

// Persistent scratch (module-load zeroed; last block restores zeros each call)
__device__ float        g_ss[NB * NSEG];
__device__ float        g_cn[NB * NSEG];
__device__ unsigned int g_done;

__device__ __forceinline__ void l2_prefetch(const void* p) {
    asm volatile("prefetch.global.L2 [%0];" :: "l"(p));
}

__global__ void __launch_bounds__(TPB, 4) fused_discrim_kernel(
    const float* __restrict__ pred,   // (B, 4, P) f32
    const int*   __restrict__ lab,    // (B, P) i32
    int P,
    float* __restrict__ out)
{
    __shared__ float s_ss2[8][NBIN];   // per-warp bin partials
    __shared__ float s_cn2[8][NBIN];
    __shared__ float s_ep[512];        // epilogue scratch
    __shared__ float s_red[TPB / 32];
    __shared__ int   s_last;

    const int t    = threadIdx.x;
    const int warp = t >> 5;
    const int lane = t & 31;
    const int b    = blockIdx.y;

    // 8 half2 ss accumulators + 8 half2 count accumulators (2 bins each).
    half2 ss[8], cn[8];
    #pragma unroll
    for (int r = 0; r < 8; r++) {
        ss[r] = __float2half2_rn(0.0f);
        cn[r] = __float2half2_rn(0.0f);
    }

    const float* p0 = pred + (size_t)b * 4 * P;
    const int*   l0 = lab  + (size_t)b * P;

    const int stride = GX * TPB * 4;
    for (int base = (blockIdx.x * TPB + t) * 4; base + 3 < P; base += stride) {
        int4   lv = *reinterpret_cast<const int4*>(l0 + base);
        float4 c0 = *reinterpret_cast<const float4*>(p0 + base);
        float4 c1 = *reinterpret_cast<const float4*>(p0 + (size_t)P     + base);
        float4 c2 = *reinterpret_cast<const float4*>(p0 + (size_t)2 * P + base);
        float4 c3 = *reinterpret_cast<const float4*>(p0 + (size_t)3 * P + base);

        // Prefetch TWO iterations ahead: ~2 iteration-times (~900+ cyc) in
        // flight fully covers the 577-cyc DRAM leg, so the demand load above
        // becomes an L2 hit. Past-the-end prefetch is ignored (no fault).
        {
            const int nb_ = base + 2 * stride;
            l2_prefetch(l0 + nb_);
            l2_prefetch(p0 + nb_);
            l2_prefetch(p0 + (size_t)P     + nb_);
            l2_prefetch(p0 + (size_t)2 * P + nb_);
            l2_prefetch(p0 + (size_t)3 * P + nb_);
        }

        float q0 = c0.x * c0.x; q0 = fmaf(c1.x, c1.x, q0);
        q0 = fmaf(c2.x, c2.x, q0); q0 = fmaf(c3.x, c3.x, q0);
        float q1 = c0.y * c0.y; q1 = fmaf(c1.y, c1.y, q1);
        q1 = fmaf(c2.y, c2.y, q1); q1 = fmaf(c3.y, c3.y, q1);
        float q2 = c0.z * c0.z; q2 = fmaf(c1.z, c1.z, q2);
        q2 = fmaf(c2.z, c2.z, q2); q2 = fmaf(c3.z, c3.z, q2);
        float q3 = c0.w * c0.w; q3 = fmaf(c1.w, c1.w, q3);
        q3 = fmaf(c2.w, c2.w, q3); q3 = fmaf(c3.w, c3.w, q3);

        half2 qa = __half2half2(__float2half_rn(q0));
        half2 qb = __half2half2(__float2half_rn(q1));
        half2 qc = __half2half2(__float2half_rn(q2));
        half2 qd = __half2half2(__float2half_rn(q3));
        half2 la = __half2half2(__int2half_rn(lv.x));
        half2 lb = __half2half2(__int2half_rn(lv.y));
        half2 lc = __half2half2(__int2half_rn(lv.z));
        half2 ld = __half2half2(__int2half_rn(lv.w));

        #pragma unroll
        for (int r = 0; r < 8; r++) {
            const half2 bk = __floats2half2_rn((float)(2 * r + 1),
                                               (float)(2 * r + 2));
            half2 ma = __heq2(la, bk);
            half2 mb = __heq2(lb, bk);
            half2 mc = __heq2(lc, bk);
            half2 md = __heq2(ld, bk);
            ss[r] = __hfma2(ma, qa, ss[r]);
            ss[r] = __hfma2(mb, qb, ss[r]);
            ss[r] = __hfma2(mc, qc, ss[r]);
            ss[r] = __hfma2(md, qd, ss[r]);
            cn[r] = __hadd2(cn[r], __hadd2(__hadd2(ma, mb), __hadd2(mc, md)));
        }
    }

    // Unpack to fp32, warp shfl-reduce, stash per-warp partials.
    #pragma unroll
    for (int r = 0; r < 8; r++) {
        float s0 = __low2float(ss[r]),  s1 = __high2float(ss[r]);
        float n0 = __low2float(cn[r]),  n1 = __high2float(cn[r]);
        #pragma unroll
        for (int o = 16; o >= 1; o >>= 1) {
            s0 += __shfl_down_sync(0xffffffffu, s0, o);
            s1 += __shfl_down_sync(0xffffffffu, s1, o);
            n0 += __shfl_down_sync(0xffffffffu, n0, o);
            n1 += __shfl_down_sync(0xffffffffu, n1, o);
        }
        if (lane == 0) {
            s_ss2[warp][2 * r]     = s0;  s_ss2[warp][2 * r + 1] = s1;
            s_cn2[warp][2 * r]     = n0;  s_cn2[warp][2 * r + 1] = n1;
        }
    }
    __syncthreads();

    // Cross-warp: 16 threads sum 8 warp partials per bin, commit globally.
    if (t < NBIN) {
        float ssum = 0.0f, c = 0.0f;
        #pragma unroll
        for (int w = 0; w < 8; w++) { ssum += s_ss2[w][t]; c += s_cn2[w][t]; }
        atomicAdd(&g_ss[b * NSEG + t + 1], ssum);
        atomicAdd(&g_cn[b * NSEG + t + 1], c);
    }

    // Last-block election
    if (t == 0) {
        __threadfence();
        unsigned int old = atomicAdd(&g_done, 1u);
        s_last = (old == (unsigned int)(NBLK - 1)) ? 1 : 0;
    }
    __syncthreads();
    if (!s_last) return;
    __threadfence();

    // ---- Epilogue (last block only) ----
    if (t < NB * 16) {
        int bb = t >> 4;
        int k  = (t & 15) + 1;
        float c = g_cn[bb * NSEG + k];
        float m = (c > 0.0f) ? g_ss[bb * NSEG + k] / (c * c) : 0.0f;
        s_ep[t]       = m;
        s_ep[256 + t] = c;
    }
    __syncthreads();

    float pacc = 0.0f;
    {
        int bb = t >> 4;
        int i  = (t & 15) + 1;
        int nk = 0;
        #pragma unroll
        for (int k = 1; k < NSEG; k++)
            if (s_ep[256 + bb * 16 + k - 1] > 0.0f) nk = k;
        float ci = s_ep[256 + bb * 16 + i - 1];
        float mi = s_ep[bb * 16 + i - 1];
        if (nk > 1 && ci > 0.0f) {
            float inv = 1.0f / fmaxf((float)(nk * (nk - 1)), 1.0f);
            for (int j = i + 1; j < NSEG; j++) {
                if (s_ep[256 + bb * 16 + j - 1] > 0.0f) {
                    float d = sqrtf(mi + s_ep[bb * 16 + j - 1]);
                    float u = SIGMA_DIS - d;
                    pacc += log1pf(u * u) * inv;
                }
            }
        }
    }
    #pragma unroll
    for (int o = 16; o >= 1; o >>= 1)
        pacc += __shfl_down_sync(0xffffffffu, pacc, o);
    if ((t & 31) == 0) s_red[t >> 5] = pacc;
    __syncthreads();
    if (t == 0) {
        float L = 0.0f;
        #pragma unroll
        for (int w = 0; w < TPB / 32; w++) L += s_red[w];
        out[0] = L;
    }

    // Reset scratch for the next graph replay.
    if (t < NB * NSEG) {
        g_ss[t] = 0.0f;
        g_cn[t] = 0.0f;
    }
    if (t == 0) g_done = 0u;
}

extern "C" void kernel_launch(void* const* d_in, const int* in_sizes, int n_in,
                              void* d_out, int out_size) {
    const float* pred = (const float*)d_in[0];   // (16, 4, 640, 640) f32
    const int*   lab  = (const int*)d_in[1];     // (16, 640, 640) i32
    float*       out  = (float*)d_out;

    const int P = in_sizes[1] / NB;              // 409600 pixels per image

    dim3 grid(GX, NB);
    fused_discrim_kernel<<<grid, TPB>>>(pred, lab, P, out);
}